// round 5
// baseline (speedup 1.0000x reference)
#include <cuda_runtime.h>

// SparseDenseMatMul: out[m,n] = sum_{i: rows[i]==m} vals[i] * A[cols[i], n]
// M = 100000, K = 100000, N = 64, NNZ = 1.6M
//
// Inputs (metadata order):
//   d_in[0] = vals (float, NNZ), d_in[1] = A (float, K*N),
//   d_in[2] = rows (int, NNZ),   d_in[3] = cols (int, NNZ)
// Output: float, M*N
//
// Strategy: bin nnz into fixed-capacity per-row buckets (Phase B, scalar
// atomics only), then gather-compute each output row with one warp and a
// single plain store (Phase C, atomic-free). Overflow (>64 nnz in a row,
// probability ~0 for Poisson(16)) handled by a spill list (Phase D).

#define N_COLS     64
#define M_ROWS     100000
#define BUCKET_CAP 64
#define OVF_CAP    8192

__device__ int  d_cnt[M_ROWS];
__device__ int2 d_bucket[(size_t)M_ROWS * BUCKET_CAP];   // (col, val-bits)
__device__ int  d_ovf_cnt;
__device__ int  d_ovf[OVF_CAP];

// ---------------- Phase A: zero counters ----------------
__global__ void phaseA_zero(int m) {
    int i = blockIdx.x * blockDim.x + threadIdx.x;
    if (i < m) d_cnt[i] = 0;
    if (i == 0) d_ovf_cnt = 0;
}

// ---------------- Phase B: bin nnz into per-row buckets ----------------
__global__ void __launch_bounds__(256)
phaseB_scatter(const float* __restrict__ vals,
               const int*   __restrict__ rows,
               const int*   __restrict__ cols,
               int nnz) {
    int i = blockIdx.x * blockDim.x + threadIdx.x;
    if (i >= nnz) return;
    // Issue all three loads up front so they overlap the atomic's latency.
    int   r = rows[i];
    int   c = cols[i];
    float v = vals[i];
    int pos = atomicAdd(&d_cnt[r], 1);
    if (pos < BUCKET_CAP) {
        d_bucket[(size_t)r * BUCKET_CAP + pos] = make_int2(c, __float_as_int(v));
    } else {
        int o = atomicAdd(&d_ovf_cnt, 1);
        if (o < OVF_CAP) d_ovf[o] = i;
    }
}

// ---------------- Phase C: warp-per-row gather SpMM (no atomics) -------
__global__ void __launch_bounds__(256)
phaseC_spmm(const float2* __restrict__ A2,
            float2*       __restrict__ out2,
            int m) {
    int gtid = blockIdx.x * blockDim.x + threadIdx.x;
    int w    = gtid >> 5;          // one warp per output row
    int lane = threadIdx.x & 31;
    if (w >= m) return;

    int c = __ldg(&d_cnt[w]);
    if (c > BUCKET_CAP) c = BUCKET_CAP;

    const int2* bk = d_bucket + (size_t)w * BUCKET_CAP;

    // Coalesced preload of this row's bucket entries into lane registers.
    int2 e0 = make_int2(0, 0), e1 = make_int2(0, 0);
    if (lane < c)      e0 = __ldg(&bk[lane]);
    if (lane + 32 < c) e1 = __ldg(&bk[lane + 32]);

    float accx = 0.f, accy = 0.f;   // lane owns out columns 2*lane, 2*lane+1

    int c0 = c < 32 ? c : 32;
    for (int k = 0; k < c0; k++) {
        int   col = __shfl_sync(0xffffffffu, e0.x, k);
        float v   = __int_as_float(__shfl_sync(0xffffffffu, e0.y, k));
        float2 a  = __ldg(&A2[(size_t)col * (N_COLS / 2) + lane]);
        accx = fmaf(v, a.x, accx);
        accy = fmaf(v, a.y, accy);
    }
    for (int k = 32; k < c; k++) {
        int   col = __shfl_sync(0xffffffffu, e1.x, k - 32);
        float v   = __int_as_float(__shfl_sync(0xffffffffu, e1.y, k - 32));
        float2 a  = __ldg(&A2[(size_t)col * (N_COLS / 2) + lane]);
        accx = fmaf(v, a.x, accx);
        accy = fmaf(v, a.y, accy);
    }

    out2[(size_t)w * (N_COLS / 2) + lane] = make_float2(accx, accy);
}

// ---------------- Phase D: apply spill entries (expected: none) --------
__global__ void phaseD_overflow(const float* __restrict__ vals,
                                const float* __restrict__ A,
                                const int*   __restrict__ rows,
                                const int*   __restrict__ cols,
                                float*       __restrict__ out) {
    int n = d_ovf_cnt;
    if (n > OVF_CAP) n = OVF_CAP;
    // 16 work items (one float4 slice) per spilled nnz
    for (int j = threadIdx.x; j < n * 16; j += blockDim.x) {
        int i   = d_ovf[j >> 4];
        int sub = j & 15;
        int r = rows[i];
        int c = cols[i];
        float v = vals[i];
        const float4* a4 = (const float4*)(A + (size_t)c * N_COLS);
        float4 a = a4[sub];
        float* dst = out + (size_t)r * N_COLS + sub * 4;
        asm volatile("red.global.add.v4.f32 [%0], {%1, %2, %3, %4};"
                     :: "l"(dst), "f"(a.x * v), "f"(a.y * v),
                        "f"(a.z * v), "f"(a.w * v)
                     : "memory");
    }
}

extern "C" void kernel_launch(void* const* d_in, const int* in_sizes, int n_in,
                              void* d_out, int out_size) {
    const float* vals = (const float*)d_in[0];
    const float* A    = (const float*)d_in[1];
    const int*   rows = (const int*)d_in[2];
    const int*   cols = (const int*)d_in[3];
    float*       out  = (float*)d_out;

    int nnz = in_sizes[0];
    int m   = out_size / N_COLS;
    if (m > M_ROWS) m = M_ROWS;   // scratch capacity bound (shapes are fixed)

    // Phase A: zero counters
    {
        int threads = 256;
        int blocks  = (m + threads - 1) / threads;
        phaseA_zero<<<blocks, threads>>>(m);
    }
    // Phase B: bin into buckets
    {
        int threads = 256;
        int blocks  = (nnz + threads - 1) / threads;
        phaseB_scatter<<<blocks, threads>>>(vals, rows, cols, nnz);
    }
    // Phase C: warp-per-row gather SpMM (also writes zeros for empty rows)
    {
        int threads = 256;                       // 8 warps / block
        int blocks  = (m * 32 + threads - 1) / threads;
        phaseC_spmm<<<blocks, threads>>>((const float2*)A, (float2*)out, m);
    }
    // Phase D: spill entries via vector RED (after C's plain stores)
    phaseD_overflow<<<1, 256>>>(vals, A, rows, cols, out);
}

// round 8
// speedup vs baseline: 1.1215x; 1.1215x over previous
#include <cuda_runtime.h>

// SparseDenseMatMul: out[m,n] = sum_{i: rows[i]==m} vals[i] * A[cols[i], n]
// M = 100000, K = 100000, N = 64, NNZ = 1.6M
//
// Inputs (metadata order):
//   d_in[0] = vals (float, NNZ), d_in[1] = A (float, K*N),
//   d_in[2] = rows (int, NNZ),   d_in[3] = cols (int, NNZ)
// Output: float, M*N
//
// 3-kernel pipeline:
//   A: zero per-row counters.
//   B: bin nnz into fixed-capacity per-row buckets (scalar atomics only).
//   C: one warp per output row; uniform int4 bucket reads (L1 broadcast),
//      4-wide unrolled A-row gather (high MLP), single plain 256B store.
//      Rows that overflowed the bucket scan the spill list inline (never
//      happens for Poisson(16) row degrees, kept for correctness).

#define N_COLS     64
#define M_ROWS     100000
#define BUCKET_CAP 64
#define OVF_CAP    8192

__device__ int  d_cnt[M_ROWS];
__device__ int2 d_bucket[(size_t)M_ROWS * BUCKET_CAP];   // (col, val-bits)
__device__ int  d_ovf_cnt;
__device__ int  d_ovf[OVF_CAP];

// ---------------- Phase A: zero counters ----------------
__global__ void phaseA_zero(int m4) {
    int i = blockIdx.x * blockDim.x + threadIdx.x;
    if (i < m4) ((int4*)d_cnt)[i] = make_int4(0, 0, 0, 0);
    if (i == 0) d_ovf_cnt = 0;
}

// ---------------- Phase B: bin nnz into per-row buckets ----------------
__global__ void __launch_bounds__(256)
phaseB_scatter(const float* __restrict__ vals,
               const int*   __restrict__ rows,
               const int*   __restrict__ cols,
               int nnz) {
    int i = blockIdx.x * blockDim.x + threadIdx.x;
    if (i >= nnz) return;
    // Issue all three loads up front so they overlap the atomic's latency.
    int   r = rows[i];
    int   c = cols[i];
    float v = vals[i];
    int pos = atomicAdd(&d_cnt[r], 1);
    if (pos < BUCKET_CAP) {
        d_bucket[(size_t)r * BUCKET_CAP + pos] = make_int2(c, __float_as_int(v));
    } else {
        int o = atomicAdd(&d_ovf_cnt, 1);
        if (o < OVF_CAP) d_ovf[o] = i;
    }
}

// ---------------- Phase C: warp-per-row gather SpMM (no atomics) -------
__global__ void __launch_bounds__(256)
phaseC_spmm(const float2* __restrict__ A2,
            float2*       __restrict__ out2,
            const float*  __restrict__ vals,
            const int*    __restrict__ rows,
            const int*    __restrict__ cols,
            int m) {
    int gtid = blockIdx.x * blockDim.x + threadIdx.x;
    int w    = gtid >> 5;          // one warp per output row
    int lane = threadIdx.x & 31;
    if (w >= m) return;

    int c  = __ldg(&d_cnt[w]);
    int cc = c < BUCKET_CAP ? c : BUCKET_CAP;

    // Bucket rows are 512B-aligned; read as int4 = 2 entries per 16B load.
    // All lanes load the same address -> L1 broadcast, one sector.
    const int4* bk4 = (const int4*)(d_bucket + (size_t)w * BUCKET_CAP);

    float accx = 0.f, accy = 0.f;   // lane owns out columns 2*lane, 2*lane+1

    int k = 0;
    // 4 entries per iteration: 2 uniform int4 loads + 4 independent gathers.
    for (; k + 4 <= cc; k += 4) {
        int4 p = __ldg(&bk4[k >> 1]);       // entries k, k+1: (c0,v0,c1,v1)
        int4 q = __ldg(&bk4[(k >> 1) + 1]); // entries k+2, k+3
        float2 a0 = __ldg(&A2[(size_t)p.x * (N_COLS / 2) + lane]);
        float2 a1 = __ldg(&A2[(size_t)p.z * (N_COLS / 2) + lane]);
        float2 a2 = __ldg(&A2[(size_t)q.x * (N_COLS / 2) + lane]);
        float2 a3 = __ldg(&A2[(size_t)q.z * (N_COLS / 2) + lane]);
        float v0 = __int_as_float(p.y), v1 = __int_as_float(p.w);
        float v2 = __int_as_float(q.y), v3 = __int_as_float(q.w);
        accx = fmaf(v0, a0.x, accx);  accy = fmaf(v0, a0.y, accy);
        accx = fmaf(v1, a1.x, accx);  accy = fmaf(v1, a1.y, accy);
        accx = fmaf(v2, a2.x, accx);  accy = fmaf(v2, a2.y, accy);
        accx = fmaf(v3, a3.x, accx);  accy = fmaf(v3, a3.y, accy);
    }
    // Remainder (0-3 entries).
    const int2* bk = (const int2*)bk4;
    for (; k < cc; k++) {
        int2 e = __ldg(&bk[k]);
        float v  = __int_as_float(e.y);
        float2 a = __ldg(&A2[(size_t)e.x * (N_COLS / 2) + lane]);
        accx = fmaf(v, a.x, accx);  accy = fmaf(v, a.y, accy);
    }

    // Spill entries for this row (expected: never taken).
    if (c > BUCKET_CAP) {
        int n = d_ovf_cnt;
        if (n > OVF_CAP) n = OVF_CAP;
        for (int j = 0; j < n; j++) {
            int i = d_ovf[j];
            if (rows[i] == w) {
                float v  = vals[i];
                float2 a = __ldg(&A2[(size_t)cols[i] * (N_COLS / 2) + lane]);
                accx = fmaf(v, a.x, accx);  accy = fmaf(v, a.y, accy);
            }
        }
    }

    out2[(size_t)w * (N_COLS / 2) + lane] = make_float2(accx, accy);
}

extern "C" void kernel_launch(void* const* d_in, const int* in_sizes, int n_in,
                              void* d_out, int out_size) {
    const float* vals = (const float*)d_in[0];
    const float* A    = (const float*)d_in[1];
    const int*   rows = (const int*)d_in[2];
    const int*   cols = (const int*)d_in[3];
    float*       out  = (float*)d_out;

    int nnz = in_sizes[0];
    int m   = out_size / N_COLS;
    if (m > M_ROWS) m = M_ROWS;   // scratch capacity bound (shapes are fixed)

    // Phase A: zero counters (int4-vectorized; M_ROWS % 4 == 0)
    {
        int m4      = (m + 3) / 4;
        int threads = 256;
        int blocks  = (m4 + threads - 1) / threads;
        phaseA_zero<<<blocks, threads>>>(m4);
    }
    // Phase B: bin into buckets
    {
        int threads = 256;
        int blocks  = (nnz + threads - 1) / threads;
        phaseB_scatter<<<blocks, threads>>>(vals, rows, cols, nnz);
    }
    // Phase C: warp-per-row gather SpMM (also writes zeros for empty rows,
    // and applies spill entries inline)
    {
        int threads = 256;                       // 8 warps / block
        int blocks  = (m * 32 + threads - 1) / threads;
        phaseC_spmm<<<blocks, threads>>>((const float2*)A, (float2*)out,
                                         vals, rows, cols, m);
    }
}

// round 10
// speedup vs baseline: 1.1581x; 1.0327x over previous
#include <cuda_runtime.h>

// SparseDenseMatMul: out[m,n] = sum_{i: rows[i]==m} vals[i] * A[cols[i], n]
// M = 100000, K = 100000, N = 64, NNZ = 1.6M
//
// Inputs (metadata order):
//   d_in[0] = vals (float, NNZ), d_in[1] = A (float, K*N),
//   d_in[2] = rows (int, NNZ),   d_in[3] = cols (int, NNZ)
// Output: float, M*N
//
// 2-kernel pipeline (counter-zeroing kernel eliminated):
//   B: bin nnz into fixed-capacity per-row buckets (scalar ticket atomics).
//      Counters start zero (module-load zero-init on first call; phase C
//      restores them to zero on every call thereafter).
//   C: one warp per output row; uniform int4 bucket reads (L1 broadcast),
//      8-wide unrolled A-row gather (high MLP), single plain 256B store,
//      then resets the row's counter for the next invocation.
//      Rows that overflowed the bucket scan the spill list inline (never
//      happens: max row degree ~40 for binomial(1.6M, 1e-5) << 64).

#define N_COLS     64
#define M_ROWS     100000
#define BUCKET_CAP 64
#define OVF_CAP    8192

__device__ int  d_cnt[M_ROWS];                           // zero-initialized
__device__ int2 d_bucket[(size_t)M_ROWS * BUCKET_CAP];   // (col, val-bits)
__device__ int  d_ovf_cnt;                               // zero-initialized
__device__ int  d_ovf[OVF_CAP];

// ---------------- Phase B: bin nnz into per-row buckets ----------------
// 2 nnz per thread, vectorized index loads.
__global__ void __launch_bounds__(256)
phaseB_scatter(const float2* __restrict__ vals2,
               const int2*   __restrict__ rows2,
               const int2*   __restrict__ cols2,
               int nnz) {
    int t  = blockIdx.x * blockDim.x + threadIdx.x;
    int i0 = t * 2;
    if (i0 >= nnz) return;

    int2   r2 = rows2[t];
    int2   c2 = cols2[t];
    float2 v2 = vals2[t];

    {
        int pos = atomicAdd(&d_cnt[r2.x], 1);
        if (pos < BUCKET_CAP) {
            d_bucket[(size_t)r2.x * BUCKET_CAP + pos] =
                make_int2(c2.x, __float_as_int(v2.x));
        } else {
            int o = atomicAdd(&d_ovf_cnt, 1);
            if (o < OVF_CAP) d_ovf[o] = i0;
        }
    }
    if (i0 + 1 < nnz) {
        int pos = atomicAdd(&d_cnt[r2.y], 1);
        if (pos < BUCKET_CAP) {
            d_bucket[(size_t)r2.y * BUCKET_CAP + pos] =
                make_int2(c2.y, __float_as_int(v2.y));
        } else {
            int o = atomicAdd(&d_ovf_cnt, 1);
            if (o < OVF_CAP) d_ovf[o] = i0 + 1;
        }
    }
}

// ---------------- Phase C: warp-per-row gather SpMM (no atomics) -------
__global__ void __launch_bounds__(256)
phaseC_spmm(const float2* __restrict__ A2,
            float2*       __restrict__ out2,
            const float*  __restrict__ vals,
            const int*    __restrict__ rows,
            const int*    __restrict__ cols,
            int m) {
    int gtid = blockIdx.x * blockDim.x + threadIdx.x;
    int w    = gtid >> 5;          // one warp per output row
    int lane = threadIdx.x & 31;
    if (w >= m) return;

    int c  = __ldg(&d_cnt[w]);
    int cc = c < BUCKET_CAP ? c : BUCKET_CAP;

    // Bucket rows are 512B-aligned; read as int4 = 2 entries per 16B load.
    // All lanes load the same address -> L1 broadcast, one sector.
    const int4* bk4 = (const int4*)(d_bucket + (size_t)w * BUCKET_CAP);

    float accx = 0.f, accy = 0.f;   // lane owns out columns 2*lane, 2*lane+1

    int k = 0;
    // 8 entries per iteration: 4 uniform int4 loads + 8 independent gathers.
    for (; k + 8 <= cc; k += 8) {
        int h = k >> 1;
        int4 p0 = __ldg(&bk4[h + 0]);
        int4 p1 = __ldg(&bk4[h + 1]);
        int4 p2 = __ldg(&bk4[h + 2]);
        int4 p3 = __ldg(&bk4[h + 3]);
        float2 a0 = __ldg(&A2[(size_t)p0.x * (N_COLS / 2) + lane]);
        float2 a1 = __ldg(&A2[(size_t)p0.z * (N_COLS / 2) + lane]);
        float2 a2 = __ldg(&A2[(size_t)p1.x * (N_COLS / 2) + lane]);
        float2 a3 = __ldg(&A2[(size_t)p1.z * (N_COLS / 2) + lane]);
        float2 a4 = __ldg(&A2[(size_t)p2.x * (N_COLS / 2) + lane]);
        float2 a5 = __ldg(&A2[(size_t)p2.z * (N_COLS / 2) + lane]);
        float2 a6 = __ldg(&A2[(size_t)p3.x * (N_COLS / 2) + lane]);
        float2 a7 = __ldg(&A2[(size_t)p3.z * (N_COLS / 2) + lane]);
        accx = fmaf(__int_as_float(p0.y), a0.x, accx);
        accy = fmaf(__int_as_float(p0.y), a0.y, accy);
        accx = fmaf(__int_as_float(p0.w), a1.x, accx);
        accy = fmaf(__int_as_float(p0.w), a1.y, accy);
        accx = fmaf(__int_as_float(p1.y), a2.x, accx);
        accy = fmaf(__int_as_float(p1.y), a2.y, accy);
        accx = fmaf(__int_as_float(p1.w), a3.x, accx);
        accy = fmaf(__int_as_float(p1.w), a3.y, accy);
        accx = fmaf(__int_as_float(p2.y), a4.x, accx);
        accy = fmaf(__int_as_float(p2.y), a4.y, accy);
        accx = fmaf(__int_as_float(p2.w), a5.x, accx);
        accy = fmaf(__int_as_float(p2.w), a5.y, accy);
        accx = fmaf(__int_as_float(p3.y), a6.x, accx);
        accy = fmaf(__int_as_float(p3.y), a6.y, accy);
        accx = fmaf(__int_as_float(p3.w), a7.x, accx);
        accy = fmaf(__int_as_float(p3.w), a7.y, accy);
    }
    // 2-wide tail.
    for (; k + 2 <= cc; k += 2) {
        int4 p = __ldg(&bk4[k >> 1]);
        float2 a0 = __ldg(&A2[(size_t)p.x * (N_COLS / 2) + lane]);
        float2 a1 = __ldg(&A2[(size_t)p.z * (N_COLS / 2) + lane]);
        accx = fmaf(__int_as_float(p.y), a0.x, accx);
        accy = fmaf(__int_as_float(p.y), a0.y, accy);
        accx = fmaf(__int_as_float(p.w), a1.x, accx);
        accy = fmaf(__int_as_float(p.w), a1.y, accy);
    }
    // Scalar tail (0-1 entries).
    if (k < cc) {
        int2 e = __ldg(&((const int2*)bk4)[k]);
        float2 a = __ldg(&A2[(size_t)e.x * (N_COLS / 2) + lane]);
        accx = fmaf(__int_as_float(e.y), a.x, accx);
        accy = fmaf(__int_as_float(e.y), a.y, accy);
    }

    // Spill entries for this row (unreachable for this dataset: max row
    // degree ~40 << BUCKET_CAP; kept for correctness).
    if (c > BUCKET_CAP) {
        int n = d_ovf_cnt;
        if (n > OVF_CAP) n = OVF_CAP;
        for (int j = 0; j < n; j++) {
            int i = d_ovf[j];
            if (rows[i] == w) {
                float v  = vals[i];
                float2 a = __ldg(&A2[(size_t)cols[i] * (N_COLS / 2) + lane]);
                accx = fmaf(v, a.x, accx);  accy = fmaf(v, a.y, accy);
            }
        }
    }

    out2[(size_t)w * (N_COLS / 2) + lane] = make_float2(accx, accy);

    // Restore state for the next invocation / graph replay.
    if (lane == 0) d_cnt[w] = 0;
    if (gtid == 0) d_ovf_cnt = 0;
}

extern "C" void kernel_launch(void* const* d_in, const int* in_sizes, int n_in,
                              void* d_out, int out_size) {
    const float* vals = (const float*)d_in[0];
    const float* A    = (const float*)d_in[1];
    const int*   rows = (const int*)d_in[2];
    const int*   cols = (const int*)d_in[3];
    float*       out  = (float*)d_out;

    int nnz = in_sizes[0];
    int m   = out_size / N_COLS;
    if (m > M_ROWS) m = M_ROWS;   // scratch capacity bound (shapes are fixed)

    // Phase B: bin into buckets (2 nnz per thread)
    {
        int threads = 256;
        int pairs   = (nnz + 1) / 2;
        int blocks  = (pairs + threads - 1) / threads;
        phaseB_scatter<<<blocks, threads>>>((const float2*)vals,
                                            (const int2*)rows,
                                            (const int2*)cols, nnz);
    }
    // Phase C: warp-per-row gather SpMM (also writes zeros for empty rows,
    // applies spill entries inline, and resets counters for next call)
    {
        int threads = 256;                       // 8 warps / block
        int blocks  = (m * 32 + threads - 1) / threads;
        phaseC_spmm<<<blocks, threads>>>((const float2*)A, (float2*)out,
                                         vals, rows, cols, m);
    }
}

// round 11
// speedup vs baseline: 1.2353x; 1.0666x over previous
#include <cuda_runtime.h>

// SparseDenseMatMul: out[m,n] = sum_{i: rows[i]==m} vals[i] * A[cols[i], n]
// M = 100000, K = 100000, N = 64, NNZ = 1.6M
//
// Inputs (metadata order):
//   d_in[0] = vals (float, NNZ), d_in[1] = A (float, K*N),
//   d_in[2] = rows (int, NNZ),   d_in[3] = cols (int, NNZ)
// Output: float, M*N
//
// 2-kernel pipeline:
//   B: bin nnz into fixed-capacity per-row buckets (scalar ticket atomics).
//      Counters start zero (module zero-init on first call; phase C restores
//      them to zero every call).
//   C: HALF-WARP per output row (16 lanes x float4 = 64 cols), so each warp
//      computes two adjacent rows concurrently: one uniform int2 counter
//      load, shared gather LDG instructions, 512B contiguous store.
//      8-entry unrolled gather loop for MLP. Overflow rows (never occur:
//      max degree ~40 << 64) scan the spill list inline.

#define N_COLS     64
#define M_ROWS     100000
#define BUCKET_CAP 64
#define OVF_CAP    8192

__device__ int  d_cnt[M_ROWS];                           // zero-initialized
__device__ int2 d_bucket[(size_t)M_ROWS * BUCKET_CAP];   // (col, val-bits)
__device__ int  d_ovf_cnt;                               // zero-initialized
__device__ int  d_ovf[OVF_CAP];

// ---------------- Phase B: bin nnz into per-row buckets ----------------
__global__ void __launch_bounds__(256)
phaseB_scatter(const float2* __restrict__ vals2,
               const int2*   __restrict__ rows2,
               const int2*   __restrict__ cols2,
               int nnz) {
    int t  = blockIdx.x * blockDim.x + threadIdx.x;
    int i0 = t * 2;
    if (i0 >= nnz) return;

    int2   r2 = rows2[t];
    int2   c2 = cols2[t];
    float2 v2 = vals2[t];

    {
        int pos = atomicAdd(&d_cnt[r2.x], 1);
        if (pos < BUCKET_CAP) {
            d_bucket[(size_t)r2.x * BUCKET_CAP + pos] =
                make_int2(c2.x, __float_as_int(v2.x));
        } else {
            int o = atomicAdd(&d_ovf_cnt, 1);
            if (o < OVF_CAP) d_ovf[o] = i0;
        }
    }
    if (i0 + 1 < nnz) {
        int pos = atomicAdd(&d_cnt[r2.y], 1);
        if (pos < BUCKET_CAP) {
            d_bucket[(size_t)r2.y * BUCKET_CAP + pos] =
                make_int2(c2.y, __float_as_int(v2.y));
        } else {
            int o = atomicAdd(&d_ovf_cnt, 1);
            if (o < OVF_CAP) d_ovf[o] = i0 + 1;
        }
    }
}

// ---------------- Phase C: half-warp-per-row gather SpMM ---------------
__global__ void __launch_bounds__(256)
phaseC_spmm(const float4* __restrict__ A4,
            float4*       __restrict__ out4,
            const float*  __restrict__ vals,
            const int*    __restrict__ rows,
            const int*    __restrict__ cols,
            int m) {
    int gtid = blockIdx.x * blockDim.x + threadIdx.x;
    int w    = gtid >> 5;             // warp id: handles rows 2w, 2w+1
    int lane = threadIdx.x & 31;
    int half = lane >> 4;             // which row of the pair
    int sub  = lane & 15;             // float4 slice within the row
    int r0   = w << 1;
    if (r0 >= m) return;
    int row  = r0 + half;             // row >= m only possible if m odd;
                                      // d_cnt has M_ROWS capacity so the
                                      // int2 read below stays in bounds.

    // Both rows' counters with one uniform 8B load (r0 even -> aligned).
    int2 cnt2 = __ldg((const int2*)(d_cnt + r0));
    int c  = half ? cnt2.y : cnt2.x;
    if (row >= m) c = 0;
    int cc = c < BUCKET_CAP ? c : BUCKET_CAP;

    // Bucket for this half's row; 512B-aligned, int4 = 2 entries/load,
    // uniform within the half-warp (L1 broadcast).
    const int4* bk4 = (const int4*)(d_bucket + (size_t)row * BUCKET_CAP);

    float4 acc = make_float4(0.f, 0.f, 0.f, 0.f);

    int k = 0;
    // 8 entries per iteration: 4 uniform int4 loads + 8 independent gathers
    // (per half; warp-wide each LDG instruction serves both rows).
    for (; k + 8 <= cc; k += 8) {
        int h = k >> 1;
        int4 p0 = __ldg(&bk4[h + 0]);
        int4 p1 = __ldg(&bk4[h + 1]);
        int4 p2 = __ldg(&bk4[h + 2]);
        int4 p3 = __ldg(&bk4[h + 3]);
        float4 a0 = __ldg(&A4[(size_t)p0.x * 16 + sub]);
        float4 a1 = __ldg(&A4[(size_t)p0.z * 16 + sub]);
        float4 a2 = __ldg(&A4[(size_t)p1.x * 16 + sub]);
        float4 a3 = __ldg(&A4[(size_t)p1.z * 16 + sub]);
        float4 a4 = __ldg(&A4[(size_t)p2.x * 16 + sub]);
        float4 a5 = __ldg(&A4[(size_t)p2.z * 16 + sub]);
        float4 a6 = __ldg(&A4[(size_t)p3.x * 16 + sub]);
        float4 a7 = __ldg(&A4[(size_t)p3.z * 16 + sub]);
        float v0 = __int_as_float(p0.y), v1 = __int_as_float(p0.w);
        float v2 = __int_as_float(p1.y), v3 = __int_as_float(p1.w);
        float v4 = __int_as_float(p2.y), v5 = __int_as_float(p2.w);
        float v6 = __int_as_float(p3.y), v7 = __int_as_float(p3.w);
        acc.x = fmaf(v0, a0.x, acc.x); acc.y = fmaf(v0, a0.y, acc.y);
        acc.z = fmaf(v0, a0.z, acc.z); acc.w = fmaf(v0, a0.w, acc.w);
        acc.x = fmaf(v1, a1.x, acc.x); acc.y = fmaf(v1, a1.y, acc.y);
        acc.z = fmaf(v1, a1.z, acc.z); acc.w = fmaf(v1, a1.w, acc.w);
        acc.x = fmaf(v2, a2.x, acc.x); acc.y = fmaf(v2, a2.y, acc.y);
        acc.z = fmaf(v2, a2.z, acc.z); acc.w = fmaf(v2, a2.w, acc.w);
        acc.x = fmaf(v3, a3.x, acc.x); acc.y = fmaf(v3, a3.y, acc.y);
        acc.z = fmaf(v3, a3.z, acc.z); acc.w = fmaf(v3, a3.w, acc.w);
        acc.x = fmaf(v4, a4.x, acc.x); acc.y = fmaf(v4, a4.y, acc.y);
        acc.z = fmaf(v4, a4.z, acc.z); acc.w = fmaf(v4, a4.w, acc.w);
        acc.x = fmaf(v5, a5.x, acc.x); acc.y = fmaf(v5, a5.y, acc.y);
        acc.z = fmaf(v5, a5.z, acc.z); acc.w = fmaf(v5, a5.w, acc.w);
        acc.x = fmaf(v6, a6.x, acc.x); acc.y = fmaf(v6, a6.y, acc.y);
        acc.z = fmaf(v6, a6.z, acc.z); acc.w = fmaf(v6, a6.w, acc.w);
        acc.x = fmaf(v7, a7.x, acc.x); acc.y = fmaf(v7, a7.y, acc.y);
        acc.z = fmaf(v7, a7.z, acc.z); acc.w = fmaf(v7, a7.w, acc.w);
    }
    // 2-wide tail.
    for (; k + 2 <= cc; k += 2) {
        int4 p = __ldg(&bk4[k >> 1]);
        float4 a0 = __ldg(&A4[(size_t)p.x * 16 + sub]);
        float4 a1 = __ldg(&A4[(size_t)p.z * 16 + sub]);
        float v0 = __int_as_float(p.y), v1 = __int_as_float(p.w);
        acc.x = fmaf(v0, a0.x, acc.x); acc.y = fmaf(v0, a0.y, acc.y);
        acc.z = fmaf(v0, a0.z, acc.z); acc.w = fmaf(v0, a0.w, acc.w);
        acc.x = fmaf(v1, a1.x, acc.x); acc.y = fmaf(v1, a1.y, acc.y);
        acc.z = fmaf(v1, a1.z, acc.z); acc.w = fmaf(v1, a1.w, acc.w);
    }
    // Scalar tail (0-1 entries).
    if (k < cc) {
        int2 e = __ldg(&((const int2*)bk4)[k]);
        float v  = __int_as_float(e.y);
        float4 a = __ldg(&A4[(size_t)e.x * 16 + sub]);
        acc.x = fmaf(v, a.x, acc.x); acc.y = fmaf(v, a.y, acc.y);
        acc.z = fmaf(v, a.z, acc.z); acc.w = fmaf(v, a.w, acc.w);
    }

    // Spill entries (unreachable for this dataset; kept for correctness).
    if (c > BUCKET_CAP) {
        int n = d_ovf_cnt;
        if (n > OVF_CAP) n = OVF_CAP;
        for (int j = 0; j < n; j++) {
            int i = d_ovf[j];
            if (rows[i] == row) {
                float v  = vals[i];
                float4 a = __ldg(&A4[(size_t)cols[i] * 16 + sub]);
                acc.x = fmaf(v, a.x, acc.x); acc.y = fmaf(v, a.y, acc.y);
                acc.z = fmaf(v, a.z, acc.z); acc.w = fmaf(v, a.w, acc.w);
            }
        }
    }

    if (row < m) {
        out4[(size_t)row * 16 + sub] = acc;      // warp-wide 512B store
        if (sub == 0) d_cnt[row] = 0;            // reset for next call
    }
    if (gtid == 0) d_ovf_cnt = 0;
}

extern "C" void kernel_launch(void* const* d_in, const int* in_sizes, int n_in,
                              void* d_out, int out_size) {
    const float* vals = (const float*)d_in[0];
    const float* A    = (const float*)d_in[1];
    const int*   rows = (const int*)d_in[2];
    const int*   cols = (const int*)d_in[3];
    float*       out  = (float*)d_out;

    int nnz = in_sizes[0];
    int m   = out_size / N_COLS;
    if (m > M_ROWS) m = M_ROWS;   // scratch capacity bound (shapes are fixed)

    // Phase B: bin into buckets (2 nnz per thread)
    {
        int threads = 256;
        int pairs   = (nnz + 1) / 2;
        int blocks  = (pairs + threads - 1) / threads;
        phaseB_scatter<<<blocks, threads>>>((const float2*)vals,
                                            (const int2*)rows,
                                            (const int2*)cols, nnz);
    }
    // Phase C: half-warp-per-row gather SpMM (2 rows per warp)
    {
        int threads   = 256;                     // 8 warps = 16 rows / block
        int row_pairs = (m + 1) / 2;
        int blocks    = (row_pairs * 32 + threads - 1) / threads;
        phaseC_spmm<<<blocks, threads>>>((const float4*)A, (float4*)out,
                                         vals, rows, cols, m);
    }
}